// round 2
// baseline (speedup 1.0000x reference)
#include <cuda_runtime.h>
#include <float.h>
#include <stdint.h>

#define B_   4
#define N_   2048
#define DIM_ 256
#define H_   8
#define HD_  32
#define M_   4
#define S_   2052          // N + M
#define TOPK_ 32
#define ROWS_ (B_*N_)      // 8192

// ---------------- scratch (no cudaMalloc allowed) ----------------
__device__ float g_q[B_*H_*N_*HD_];      // 8 MB
__device__ float g_k[B_*H_*N_*HD_];      // 8 MB
__device__ float g_v[B_*H_*N_*HD_];      // 8 MB
__device__ float g_attn[B_*N_*H_*HD_];   // 8 MB  [B,N,H*HD]

// monotonic float -> uint mapping (order-preserving, bijective)
__device__ __forceinline__ unsigned enc_f(float f) {
    unsigned u = __float_as_uint(f);
    return u ^ ((u & 0x80000000u) ? 0xFFFFFFFFu : 0x80000000u);
}

// =====================================================================
// GEMM 1: qkv = x @ w_qkv + b_qkv, scattered into g_q/g_k/g_v [B,H,N,HD]
// X: [8192,256], W: [256,768]. Tile 128x128, BK=16, 256 thr, 8x8 micro.
// =====================================================================
__global__ __launch_bounds__(256) void gemm_qkv_kernel(
    const float* __restrict__ X, const float* __restrict__ W,
    const float* __restrict__ bias)
{
    __shared__ __align__(16) float As[16 * 132];   // [k][m], padded
    __shared__ __align__(16) float Bs[16 * 128];   // [k][n]
    const int tid = threadIdx.x;
    const int rowBase = blockIdx.y * 128;
    const int colBase = blockIdx.x * 128;
    const int ty = tid >> 4, tx = tid & 15;

    float acc[8][8];
#pragma unroll
    for (int i = 0; i < 8; i++)
#pragma unroll
        for (int j = 0; j < 8; j++) acc[i][j] = 0.f;

    for (int kb = 0; kb < DIM_; kb += 16) {
#pragma unroll
        for (int i = 0; i < 2; i++) {
            int f4 = tid + i * 256;            // 0..511
            int row = f4 >> 2;                 // 4 float4 per 16-wide row
            int kc = (f4 & 3) << 2;
            float4 v = *reinterpret_cast<const float4*>(
                X + (size_t)(rowBase + row) * DIM_ + kb + kc);
            As[(kc + 0) * 132 + row] = v.x;
            As[(kc + 1) * 132 + row] = v.y;
            As[(kc + 2) * 132 + row] = v.z;
            As[(kc + 3) * 132 + row] = v.w;
        }
#pragma unroll
        for (int i = 0; i < 2; i++) {
            int f4 = tid + i * 256;
            int kr = f4 >> 5;                  // 32 float4 per 128-wide row
            int cc = (f4 & 31) << 2;
            *reinterpret_cast<float4*>(&Bs[kr * 128 + cc]) =
                *reinterpret_cast<const float4*>(
                    W + (size_t)(kb + kr) * 768 + colBase + cc);
        }
        __syncthreads();
#pragma unroll
        for (int kk = 0; kk < 16; kk++) {
            float a[8], b[8];
            *reinterpret_cast<float4*>(&a[0]) =
                *reinterpret_cast<const float4*>(&As[kk * 132 + ty * 8]);
            *reinterpret_cast<float4*>(&a[4]) =
                *reinterpret_cast<const float4*>(&As[kk * 132 + ty * 8 + 4]);
            *reinterpret_cast<float4*>(&b[0]) =
                *reinterpret_cast<const float4*>(&Bs[kk * 128 + tx * 8]);
            *reinterpret_cast<float4*>(&b[4]) =
                *reinterpret_cast<const float4*>(&Bs[kk * 128 + tx * 8 + 4]);
#pragma unroll
            for (int i = 0; i < 8; i++)
#pragma unroll
                for (int j = 0; j < 8; j++) acc[i][j] += a[i] * b[j];
        }
        __syncthreads();
    }

#pragma unroll
    for (int i = 0; i < 8; i++) {
        int r = rowBase + ty * 8 + i;
        int bb = r >> 11;                  // / N_
        int n = r & (N_ - 1);
#pragma unroll
        for (int j = 0; j < 8; j++) {
            int c = colBase + tx * 8 + j;
            float val = acc[i][j] + bias[c];
            int t = c >> 8;                // 0:q 1:k 2:v
            int h = (c >> 5) & 7;
            int d = c & 31;
            float* dst = (t == 0) ? g_q : (t == 1) ? g_k : g_v;
            dst[(((size_t)(bb * H_ + h)) * N_ + n) * HD_ + d] = val;
        }
    }
}

// =====================================================================
// Attention: one block (128 thr) per (b,h,n) query.
// scores -> exact radix select of 32nd largest -> softmax over >= thr ->
// sparse AV -> g_attn [B,N,H*HD]
// =====================================================================
__global__ __launch_bounds__(128) void attn_kernel(
    const float* __restrict__ scale,
    const float* __restrict__ mem_k,
    const float* __restrict__ mem_v)
{
    __shared__ __align__(16) float sc[S_];
    __shared__ __align__(16) float qsh[HD_];
    __shared__ unsigned hist[256];
    __shared__ unsigned scanA[256];
    __shared__ unsigned scanB[256];
    __shared__ float red[4];
    __shared__ float s_rowmax;
    __shared__ unsigned s_rem, s_prefix, s_cnt;
    __shared__ int   kept_idx[256];
    __shared__ float kept_w[256];
    __shared__ float partial[4][HD_];

    const int tid = threadIdx.x;
    const int bid = blockIdx.x;
    const int n = bid & (N_ - 1);
    const int h = (bid >> 11) & (H_ - 1);
    const int b = bid >> 14;

    if (tid < HD_)
        qsh[tid] = g_q[(((size_t)(b * H_ + h)) * N_ + n) * HD_ + tid];
    if (tid == 0) { s_rem = TOPK_; s_prefix = 0u; s_cnt = 0u; }
    __syncthreads();

    const float sfac = 0.17677669529663687f * scale[h];  // hd^-0.5 * scale
    const float* kbase = g_k + ((size_t)(b * H_ + h)) * N_ * HD_;

    // ---- scores + row max ----
    float lmax = -FLT_MAX;
    for (int s = tid; s < S_; s += 128) {
        const float* kp = (s < N_) ? (kbase + (size_t)s * HD_)
                                   : (mem_k + (h * M_ + (s - N_)) * HD_);
        float dot = 0.f;
#pragma unroll
        for (int j = 0; j < 8; j++) {
            float4 kk = reinterpret_cast<const float4*>(kp)[j];
            float4 qq = reinterpret_cast<const float4*>(qsh)[j];
            dot += qq.x * kk.x + qq.y * kk.y + qq.z * kk.z + qq.w * kk.w;
        }
        float v = dot * sfac;
        if (s == n) v = -FLT_MAX;          // diagonal mask
        sc[s] = v;
        lmax = fmaxf(lmax, v);
    }
#pragma unroll
    for (int o = 16; o; o >>= 1) lmax = fmaxf(lmax, __shfl_xor_sync(0xffffffffu, lmax, o));
    if ((tid & 31) == 0) red[tid >> 5] = lmax;
    __syncthreads();
    if (tid == 0)
        s_rowmax = fmaxf(fmaxf(red[0], red[1]), fmaxf(red[2], red[3]));
    __syncthreads();

    // ---- exact radix select: 32nd largest value (8 bits / pass, MSB first) ----
    for (int pass = 3; pass >= 0; --pass) {
        const unsigned pref = s_prefix;     // safe: last write behind a barrier
        const unsigned rem = s_rem;
        for (int i = tid; i < 256; i += 128) hist[i] = 0u;
        __syncthreads();
        const int shift = pass * 8;
        for (int s = tid; s < S_; s += 128) {
            unsigned key = enc_f(sc[s]);
            bool ok = (pass == 3) || ((key >> (shift + 8)) == (pref >> (shift + 8)));
            if (ok) atomicAdd(&hist[(key >> shift) & 0xFFu], 1u);
        }
        __syncthreads();
        // inclusive suffix scan over 256 bins (Hillis-Steele, ping-pong)
        unsigned* src = scanA; unsigned* dst = scanB;
        for (int i = tid; i < 256; i += 128) scanA[i] = hist[i];
        __syncthreads();
        for (int off = 1; off < 256; off <<= 1) {
            for (int i = tid; i < 256; i += 128)
                dst[i] = src[i] + ((i + off < 256) ? src[i + off] : 0u);
            __syncthreads();
            unsigned* t = src; src = dst; dst = t;
        }
        // pick the bin containing the rem-th largest
        for (int i = tid; i < 256; i += 128) {
            unsigned ge  = src[i];
            unsigned gen = (i < 255) ? src[i + 1] : 0u;
            if (ge >= rem && gen < rem) {
                s_prefix = pref | ((unsigned)i << shift);
                s_rem = rem - gen;
            }
        }
        __syncthreads();
    }
    const unsigned uthr = s_prefix;          // exact key of kth largest
    const float rowmax = s_rowmax;

    // ---- gather survivors (score >= vk), softmax numerator ----
    float lsum = 0.f;
    for (int s = tid; s < S_; s += 128) {
        float v = sc[s];
        if (enc_f(v) >= uthr) {
            float w = __expf(v - rowmax);
            unsigned pos = atomicAdd(&s_cnt, 1u);
            if (pos < 256u) { kept_idx[pos] = s; kept_w[pos] = w; }
            lsum += w;
        }
    }
#pragma unroll
    for (int o = 16; o; o >>= 1) lsum += __shfl_xor_sync(0xffffffffu, lsum, o);
    if ((tid & 31) == 0) red[tid >> 5] = lsum;
    __syncthreads();
    const float sum = red[0] + red[1] + red[2] + red[3];
    const int cnt = min((int)s_cnt, 256);

    // ---- sparse AV: 4 chunks x 32 dims ----
    const int d = tid & 31;
    const int chunk = tid >> 5;
    const float* vbase = g_v + ((size_t)(b * H_ + h)) * N_ * HD_;
    float acc = 0.f;
    for (int i = chunk; i < cnt; i += 4) {
        int s = kept_idx[i];
        const float* vp = (s < N_) ? (vbase + (size_t)s * HD_)
                                   : (mem_v + (h * M_ + (s - N_)) * HD_);
        acc += kept_w[i] * vp[d];
    }
    partial[chunk][d] = acc;
    __syncthreads();
    if (tid < HD_) {
        float o = partial[0][d] + partial[1][d] + partial[2][d] + partial[3][d];
        g_attn[((size_t)(b * N_ + n)) * (H_ * HD_) + h * HD_ + d] = o / sum;
    }
}

// =====================================================================
// GEMM 2: out = g_attn @ w_proj + b_proj.  [8192,256] x [256,256]
// =====================================================================
__global__ __launch_bounds__(256) void gemm_proj_kernel(
    const float* __restrict__ W, const float* __restrict__ bias,
    float* __restrict__ out)
{
    __shared__ __align__(16) float As[16 * 132];
    __shared__ __align__(16) float Bs[16 * 128];
    const int tid = threadIdx.x;
    const int rowBase = blockIdx.y * 128;
    const int colBase = blockIdx.x * 128;
    const int ty = tid >> 4, tx = tid & 15;

    float acc[8][8];
#pragma unroll
    for (int i = 0; i < 8; i++)
#pragma unroll
        for (int j = 0; j < 8; j++) acc[i][j] = 0.f;

    for (int kb = 0; kb < 256; kb += 16) {
#pragma unroll
        for (int i = 0; i < 2; i++) {
            int f4 = tid + i * 256;
            int row = f4 >> 2;
            int kc = (f4 & 3) << 2;
            float4 v = *reinterpret_cast<const float4*>(
                g_attn + (size_t)(rowBase + row) * 256 + kb + kc);
            As[(kc + 0) * 132 + row] = v.x;
            As[(kc + 1) * 132 + row] = v.y;
            As[(kc + 2) * 132 + row] = v.z;
            As[(kc + 3) * 132 + row] = v.w;
        }
#pragma unroll
        for (int i = 0; i < 2; i++) {
            int f4 = tid + i * 256;
            int kr = f4 >> 5;
            int cc = (f4 & 31) << 2;
            *reinterpret_cast<float4*>(&Bs[kr * 128 + cc]) =
                *reinterpret_cast<const float4*>(
                    W + (size_t)(kb + kr) * 256 + colBase + cc);
        }
        __syncthreads();
#pragma unroll
        for (int kk = 0; kk < 16; kk++) {
            float a[8], b[8];
            *reinterpret_cast<float4*>(&a[0]) =
                *reinterpret_cast<const float4*>(&As[kk * 132 + ty * 8]);
            *reinterpret_cast<float4*>(&a[4]) =
                *reinterpret_cast<const float4*>(&As[kk * 132 + ty * 8 + 4]);
            *reinterpret_cast<float4*>(&b[0]) =
                *reinterpret_cast<const float4*>(&Bs[kk * 128 + tx * 8]);
            *reinterpret_cast<float4*>(&b[4]) =
                *reinterpret_cast<const float4*>(&Bs[kk * 128 + tx * 8 + 4]);
#pragma unroll
            for (int i = 0; i < 8; i++)
#pragma unroll
                for (int j = 0; j < 8; j++) acc[i][j] += a[i] * b[j];
        }
        __syncthreads();
    }

#pragma unroll
    for (int i = 0; i < 8; i++) {
        int r = rowBase + ty * 8 + i;
#pragma unroll
        for (int j = 0; j < 8; j++) {
            int c = colBase + tx * 8 + j;
            out[(size_t)r * 256 + c] = acc[i][j] + bias[c];
        }
    }
}

// =====================================================================
extern "C" void kernel_launch(void* const* d_in, const int* in_sizes, int n_in,
                              void* d_out, int out_size)
{
    const float* x      = (const float*)d_in[0];
    const float* w_qkv  = (const float*)d_in[1];
    const float* b_qkv  = (const float*)d_in[2];
    const float* w_proj = (const float*)d_in[3];
    const float* b_proj = (const float*)d_in[4];
    const float* scale  = (const float*)d_in[5];
    const float* mem_k  = (const float*)d_in[6];
    const float* mem_v  = (const float*)d_in[7];
    float* out = (float*)d_out;

    dim3 g1(768 / 128, ROWS_ / 128);          // 6 x 64
    gemm_qkv_kernel<<<g1, 256>>>(x, w_qkv, b_qkv);

    attn_kernel<<<B_ * H_ * N_, 128>>>(scale, mem_k, mem_v);

    dim3 g3(256 / 128, ROWS_ / 128);          // 2 x 64
    gemm_proj_kernel<<<g3, 256>>>(w_proj, b_proj, out);
}

// round 4
// speedup vs baseline: 2.5953x; 2.5953x over previous
#include <cuda_runtime.h>
#include <float.h>
#include <stdint.h>

#define B_   4
#define N_   2048
#define DIM_ 256
#define H_   8
#define HD_  32
#define M_   4
#define S_   2052          // N + M
#define TOPK_ 32
#define ROWS_ (B_*N_)      // 8192

#define QT_  8             // queries per block (attention)
#define KT_  128           // keys per shared tile
#define SP_  2056          // padded score row stride
#define KSTR_ 36           // padded K-tile row stride (floats)

// ---------------- scratch (no cudaMalloc allowed) ----------------
__device__ float g_q[B_*H_*N_*HD_];      // 8 MB
__device__ float g_k[B_*H_*N_*HD_];      // 8 MB
__device__ float g_v[B_*H_*N_*HD_];      // 8 MB
__device__ float g_attn[B_*N_*H_*HD_];   // 8 MB  [B,N,H*HD]

// monotonic float -> uint mapping (order-preserving, bijective)
__device__ __forceinline__ unsigned enc_f(float f) {
    unsigned u = __float_as_uint(f);
    return u ^ ((u & 0x80000000u) ? 0xFFFFFFFFu : 0x80000000u);
}

// =====================================================================
// GEMM 1: qkv = x @ w_qkv + b_qkv, scattered into g_q/g_k/g_v [B,H,N,HD]
// =====================================================================
__global__ __launch_bounds__(256) void gemm_qkv_kernel(
    const float* __restrict__ X, const float* __restrict__ W,
    const float* __restrict__ bias)
{
    __shared__ __align__(16) float As[16 * 132];   // [k][m], padded
    __shared__ __align__(16) float Bs[16 * 128];   // [k][n]
    const int tid = threadIdx.x;
    const int rowBase = blockIdx.y * 128;
    const int colBase = blockIdx.x * 128;
    const int ty = tid >> 4, tx = tid & 15;

    float acc[8][8];
#pragma unroll
    for (int i = 0; i < 8; i++)
#pragma unroll
        for (int j = 0; j < 8; j++) acc[i][j] = 0.f;

    for (int kb = 0; kb < DIM_; kb += 16) {
#pragma unroll
        for (int i = 0; i < 2; i++) {
            int f4 = tid + i * 256;
            int row = f4 >> 2;
            int kc = (f4 & 3) << 2;
            float4 v = *reinterpret_cast<const float4*>(
                X + (size_t)(rowBase + row) * DIM_ + kb + kc);
            As[(kc + 0) * 132 + row] = v.x;
            As[(kc + 1) * 132 + row] = v.y;
            As[(kc + 2) * 132 + row] = v.z;
            As[(kc + 3) * 132 + row] = v.w;
        }
#pragma unroll
        for (int i = 0; i < 2; i++) {
            int f4 = tid + i * 256;
            int kr = f4 >> 5;
            int cc = (f4 & 31) << 2;
            *reinterpret_cast<float4*>(&Bs[kr * 128 + cc]) =
                *reinterpret_cast<const float4*>(
                    W + (size_t)(kb + kr) * 768 + colBase + cc);
        }
        __syncthreads();
#pragma unroll
        for (int kk = 0; kk < 16; kk++) {
            float a[8], b[8];
            *reinterpret_cast<float4*>(&a[0]) =
                *reinterpret_cast<const float4*>(&As[kk * 132 + ty * 8]);
            *reinterpret_cast<float4*>(&a[4]) =
                *reinterpret_cast<const float4*>(&As[kk * 132 + ty * 8 + 4]);
            *reinterpret_cast<float4*>(&b[0]) =
                *reinterpret_cast<const float4*>(&Bs[kk * 128 + tx * 8]);
            *reinterpret_cast<float4*>(&b[4]) =
                *reinterpret_cast<const float4*>(&Bs[kk * 128 + tx * 8 + 4]);
#pragma unroll
            for (int i = 0; i < 8; i++)
#pragma unroll
                for (int j = 0; j < 8; j++) acc[i][j] += a[i] * b[j];
        }
        __syncthreads();
    }

#pragma unroll
    for (int i = 0; i < 8; i++) {
        int r = rowBase + ty * 8 + i;
        int bb = r >> 11;
        int n = r & (N_ - 1);
#pragma unroll
        for (int j = 0; j < 8; j++) {
            int c = colBase + tx * 8 + j;
            float val = acc[i][j] + bias[c];
            int t = c >> 8;
            int h = (c >> 5) & 7;
            int d = c & 31;
            float* dst = (t == 0) ? g_q : (t == 1) ? g_k : g_v;
            dst[(((size_t)(bb * H_ + h)) * N_ + n) * HD_ + d] = val;
        }
    }
}

// =====================================================================
// Attention: one block = 8 queries of one (b,h). 256 threads.
// Phase 1 (GEMM-style): scores[8][2052] into dyn smem via shared K tiles.
// Phase 2 (warp per query): exact radix select (warp-private, no block
//   barriers) -> fused softmax + sparse AV via ballot/shfl.
// =====================================================================
__global__ __launch_bounds__(256, 2) void attn_kernel(
    const float* __restrict__ scale,
    const float* __restrict__ mem_k,
    const float* __restrict__ mem_v)
{
    extern __shared__ __align__(16) float smem[];
    float*    sc    = smem;                       // [QT][SP_]      65792 B
    float*    qsh   = sc + QT_ * SP_;             // [QT][32]        1024 B
    float*    ktile = qsh + QT_ * 32;             // [KT][KSTR_]    18432 B
    unsigned* hist  = (unsigned*)(ktile + KT_ * KSTR_); // [QT][256]  8192 B

    const int tid = threadIdx.x;
    const int bid = blockIdx.x;
    const int qt = bid & 255;              // N_/QT_ = 256 tiles
    const int h  = (bid >> 8) & (H_ - 1);
    const int b  = bid >> 11;
    const int n0 = qt * QT_;

    const float sfac = 0.17677669529663687f * scale[h];
    const float* kbase = g_k + ((size_t)(b * H_ + h)) * N_ * HD_;
    const float* vbase = g_v + ((size_t)(b * H_ + h)) * N_ * HD_;

    // load 8 q rows (contiguous 256 floats)
    {
        const float* qb = g_q + (((size_t)(b * H_ + h)) * N_ + n0) * HD_;
        if (tid < QT_ * HD_) qsh[tid] = qb[tid];
    }

    // ---------- Phase 1: scores ----------
    const int key = tid & 127;             // key within tile
    const int qg  = tid >> 7;              // query group 0/1 -> queries qg*4..+3
    for (int tile = 0; tile < (S_ + KT_ - 1) / KT_; tile++) {
        const int base = tile * KT_;
        // stage K tile (pad stride 36 for conflict-free reads)
#pragma unroll
        for (int i = 0; i < 4; i++) {
            int f4 = tid + i * 256;        // 0..1023
            int kk = f4 >> 3;              // key in tile
            int k4 = f4 & 7;               // float4 within row
            int s = base + kk;
            float4 v = make_float4(0.f, 0.f, 0.f, 0.f);
            if (s < N_)
                v = *reinterpret_cast<const float4*>(kbase + (size_t)s * HD_ + k4 * 4);
            else if (s < S_)
                v = *reinterpret_cast<const float4*>(mem_k + (h * M_ + (s - N_)) * HD_ + k4 * 4);
            *reinterpret_cast<float4*>(&ktile[kk * KSTR_ + k4 * 4]) = v;
        }
        __syncthreads();

        float acc0 = 0.f, acc1 = 0.f, acc2 = 0.f, acc3 = 0.f;
#pragma unroll
        for (int j = 0; j < 8; j++) {
            float4 kv = *reinterpret_cast<const float4*>(&ktile[key * KSTR_ + j * 4]);
            float4 q0 = *reinterpret_cast<const float4*>(&qsh[(qg * 4 + 0) * 32 + j * 4]);
            float4 q1 = *reinterpret_cast<const float4*>(&qsh[(qg * 4 + 1) * 32 + j * 4]);
            float4 q2 = *reinterpret_cast<const float4*>(&qsh[(qg * 4 + 2) * 32 + j * 4]);
            float4 q3 = *reinterpret_cast<const float4*>(&qsh[(qg * 4 + 3) * 32 + j * 4]);
            acc0 += q0.x*kv.x + q0.y*kv.y + q0.z*kv.z + q0.w*kv.w;
            acc1 += q1.x*kv.x + q1.y*kv.y + q1.z*kv.z + q1.w*kv.w;
            acc2 += q2.x*kv.x + q2.y*kv.y + q2.z*kv.z + q2.w*kv.w;
            acc3 += q3.x*kv.x + q3.y*kv.y + q3.z*kv.z + q3.w*kv.w;
        }
        const int s = base + key;
        if (s < S_) {
            float r0 = acc0 * sfac, r1 = acc1 * sfac, r2 = acc2 * sfac, r3 = acc3 * sfac;
            if (s == n0 + qg * 4 + 0) r0 = -FLT_MAX;
            if (s == n0 + qg * 4 + 1) r1 = -FLT_MAX;
            if (s == n0 + qg * 4 + 2) r2 = -FLT_MAX;
            if (s == n0 + qg * 4 + 3) r3 = -FLT_MAX;
            sc[(qg * 4 + 0) * SP_ + s] = r0;
            sc[(qg * 4 + 1) * SP_ + s] = r1;
            sc[(qg * 4 + 2) * SP_ + s] = r2;
            sc[(qg * 4 + 3) * SP_ + s] = r3;
        }
        __syncthreads();
    }

    // ---------- Phase 2: one warp per query ----------
    const int wid  = tid >> 5;             // query index 0..7
    const int lane = tid & 31;
    float* row = sc + wid * SP_;
    unsigned* h8 = hist + wid * 256;

    unsigned prefix = 0, rem = TOPK_;
    float rowmax = -FLT_MAX;

    for (int pass = 3; pass >= 0; --pass) {
        const int shift = pass * 8;
        for (int i = lane; i < 256; i += 32) h8[i] = 0u;
        __syncwarp();
        if (pass == 3) {
            for (int s = lane; s < S_; s += 32) {
                float v = row[s];
                rowmax = fmaxf(rowmax, v);
                atomicAdd(&h8[enc_f(v) >> 24], 1u);
            }
        } else {
            const unsigned hi = prefix >> (shift + 8);
            for (int s = lane; s < S_; s += 32) {
                unsigned k = enc_f(row[s]);
                if ((k >> (shift + 8)) == hi)
                    atomicAdd(&h8[(k >> shift) & 255u], 1u);
            }
        }
        __syncwarp();
        // find bin containing the rem-th largest (suffix counts via shuffles)
        unsigned c[8], lsum = 0;
#pragma unroll
        for (int j = 0; j < 8; j++) { c[j] = h8[lane * 8 + j]; lsum += c[j]; }
        unsigned acc = lsum;
#pragma unroll
        for (int o = 1; o < 32; o <<= 1) {
            unsigned other = __shfl_down_sync(0xffffffffu, acc, o);
            if (lane + o < 32) acc += other;
        }
        unsigned run = acc - lsum;         // count of keys in bins above lane's range
        int sel = -1; unsigned newrem = 0;
#pragma unroll
        for (int j = 7; j >= 0; j--) {
            unsigned prev = run;
            run += c[j];
            if (sel < 0 && run >= rem && prev < rem) {
                sel = lane * 8 + j;
                newrem = rem - prev;
            }
        }
        unsigned bal = __ballot_sync(0xffffffffu, sel >= 0);
        int src = __ffs(bal) - 1;
        sel    = __shfl_sync(0xffffffffu, sel, src);
        newrem = __shfl_sync(0xffffffffu, newrem, src);
        prefix |= ((unsigned)sel) << shift;
        rem = newrem;
    }
    // warp-reduce rowmax
#pragma unroll
    for (int o = 16; o; o >>= 1)
        rowmax = fmaxf(rowmax, __shfl_xor_sync(0xffffffffu, rowmax, o));
    const unsigned uthr = prefix;          // exact key of kth largest

    // fused softmax + sparse AV (survivors via ballot; coalesced V loads)
    float accv = 0.f, wsum = 0.f;
    for (int s0 = 0; s0 < S_; s0 += 32) {
        const int s = s0 + lane;
        bool p = false; float w = 0.f;
        if (s < S_) {
            float v = row[s];
            if (enc_f(v) >= uthr) { p = true; w = __expf(v - rowmax); }
        }
        unsigned m = __ballot_sync(0xffffffffu, p);
        while (m) {
            int l = __ffs(m) - 1;
            m &= m - 1;
            int ss = s0 + l;
            float ww = __shfl_sync(0xffffffffu, w, l);
            wsum += ww;
            const float* vp = (ss < N_) ? (vbase + (size_t)ss * HD_)
                                        : (mem_v + (h * M_ + (ss - N_)) * HD_);
            accv += ww * vp[lane];
        }
    }
    g_attn[((size_t)(b * N_ + n0 + wid)) * (H_ * HD_) + h * HD_ + lane] = accv / wsum;
}

// =====================================================================
// GEMM 2: out = g_attn @ w_proj + b_proj.  [8192,256] x [256,256]
// =====================================================================
__global__ __launch_bounds__(256) void gemm_proj_kernel(
    const float* __restrict__ W, const float* __restrict__ bias,
    float* __restrict__ out)
{
    __shared__ __align__(16) float As[16 * 132];
    __shared__ __align__(16) float Bs[16 * 128];
    const int tid = threadIdx.x;
    const int rowBase = blockIdx.y * 128;
    const int colBase = blockIdx.x * 128;
    const int ty = tid >> 4, tx = tid & 15;

    float acc[8][8];
#pragma unroll
    for (int i = 0; i < 8; i++)
#pragma unroll
        for (int j = 0; j < 8; j++) acc[i][j] = 0.f;

    for (int kb = 0; kb < 256; kb += 16) {
#pragma unroll
        for (int i = 0; i < 2; i++) {
            int f4 = tid + i * 256;
            int row = f4 >> 2;
            int kc = (f4 & 3) << 2;
            float4 v = *reinterpret_cast<const float4*>(
                g_attn + (size_t)(rowBase + row) * 256 + kb + kc);
            As[(kc + 0) * 132 + row] = v.x;
            As[(kc + 1) * 132 + row] = v.y;
            As[(kc + 2) * 132 + row] = v.z;
            As[(kc + 3) * 132 + row] = v.w;
        }
#pragma unroll
        for (int i = 0; i < 2; i++) {
            int f4 = tid + i * 256;
            int kr = f4 >> 5;
            int cc = (f4 & 31) << 2;
            *reinterpret_cast<float4*>(&Bs[kr * 128 + cc]) =
                *reinterpret_cast<const float4*>(
                    W + (size_t)(kb + kr) * 256 + colBase + cc);
        }
        __syncthreads();
#pragma unroll
        for (int kk = 0; kk < 16; kk++) {
            float a[8], b[8];
            *reinterpret_cast<float4*>(&a[0]) =
                *reinterpret_cast<const float4*>(&As[kk * 132 + ty * 8]);
            *reinterpret_cast<float4*>(&a[4]) =
                *reinterpret_cast<const float4*>(&As[kk * 132 + ty * 8 + 4]);
            *reinterpret_cast<float4*>(&b[0]) =
                *reinterpret_cast<const float4*>(&Bs[kk * 128 + tx * 8]);
            *reinterpret_cast<float4*>(&b[4]) =
                *reinterpret_cast<const float4*>(&Bs[kk * 128 + tx * 8 + 4]);
#pragma unroll
            for (int i = 0; i < 8; i++)
#pragma unroll
                for (int j = 0; j < 8; j++) acc[i][j] += a[i] * b[j];
        }
        __syncthreads();
    }

#pragma unroll
    for (int i = 0; i < 8; i++) {
        int r = rowBase + ty * 8 + i;
#pragma unroll
        for (int j = 0; j < 8; j++) {
            int c = colBase + tx * 8 + j;
            out[(size_t)r * 256 + c] = acc[i][j] + bias[c];
        }
    }
}

// =====================================================================
extern "C" void kernel_launch(void* const* d_in, const int* in_sizes, int n_in,
                              void* d_out, int out_size)
{
    const float* x      = (const float*)d_in[0];
    const float* w_qkv  = (const float*)d_in[1];
    const float* b_qkv  = (const float*)d_in[2];
    const float* w_proj = (const float*)d_in[3];
    const float* b_proj = (const float*)d_in[4];
    const float* scale  = (const float*)d_in[5];
    const float* mem_k  = (const float*)d_in[6];
    const float* mem_v  = (const float*)d_in[7];
    float* out = (float*)d_out;

    dim3 g1(768 / 128, ROWS_ / 128);
    gemm_qkv_kernel<<<g1, 256>>>(x, w_qkv, b_qkv);

    const int smem_bytes = (QT_ * SP_ + QT_ * 32 + KT_ * KSTR_) * 4 + QT_ * 256 * 4;
    static int attr_set = 0;
    if (!attr_set) {
        cudaFuncSetAttribute(attn_kernel,
                             cudaFuncAttributeMaxDynamicSharedMemorySize, smem_bytes);
        attr_set = 1;
    }
    attn_kernel<<<B_ * H_ * (N_ / QT_), 256, smem_bytes>>>(scale, mem_k, mem_v);

    dim3 g3(256 / 128, ROWS_ / 128);
    gemm_proj_kernel<<<g3, 256>>>(w_proj, b_proj, out);
}